// round 15
// baseline (speedup 1.0000x reference)
#include <cuda_runtime.h>
#include <cstdint>

#define T_LEN 16384
#define HID   256
#define EMB   16
#define TMP   128
#define EVD   2048
#define NCTA  16          // 16-CTA cluster (non-portable size, enabled at launch)
#define NTHR  128         // threads per CTA; NCTA*NTHR = 2048 = one thread per logit row
#define NEG_SLOPE 0.01f

// Scratch (static device globals — no allocation at runtime)
__device__ float g_X[(T_LEN + 2) * TMP]; // bilstm part of layer-1 preactivation (+2 pad rows)
__device__ float g_C[EVD * TMP];         // 1 MB: event-embedding part of layer-1 preactivation
__device__ float g_W2T[TMP * EVD];       // 1 MB: W2 transposed -> [k][col]
__device__ int   g_idx[T_LEN];           // argmax index emitted at each step

// Packed fp32x2 FMA (sm_100+): d = a*b + c elementwise on two packed floats.
__device__ __forceinline__ unsigned long long fma2(unsigned long long a,
                                                   unsigned long long b,
                                                   unsigned long long c) {
    unsigned long long d;
    asm("fma.rn.f32x2 %0, %1, %2, %3;" : "=l"(d) : "l"(a), "l"(b), "l"(c));
    return d;
}
__device__ __forceinline__ float2 unpack2(unsigned long long v) {
    float2 r;
    asm("mov.b64 {%0, %1}, %2;" : "=f"(r.x), "=f"(r.y) : "l"(v));
    return r;
}
__device__ __forceinline__ unsigned long long dup2(float v) {
    unsigned long long d;
    asm("mov.b64 %0, {%1, %1};" : "=l"(d) : "f"(v));
    return d;
}

// ---------------------------------------------------------------------------
// Phase 1a: X[t][j] for 16 timesteps per CTA (W1 row read once per 16 rows).
// ---------------------------------------------------------------------------
__global__ void __launch_bounds__(128) x_kernel(const float* __restrict__ bilstm,
                                                const float* __restrict__ W1,
                                                const float* __restrict__ b1) {
    __shared__ __align__(16) float rows[16][HID];
    const int t0 = blockIdx.x * 16;
    const int j  = threadIdx.x;

    for (int q = j; q < 16 * HID; q += 128) {
        rows[q >> 8][q & 255] = bilstm[t0 * HID + q];
    }
    __syncthreads();

    const float4* w4 = reinterpret_cast<const float4*>(W1 + j * (HID + EMB));
    float acc[16];
    const float bb = b1[j];
#pragma unroll
    for (int rr = 0; rr < 16; rr++) acc[rr] = bb;

#pragma unroll 4
    for (int k = 0; k < HID / 4; k++) {
        const float4 w = w4[k];
#pragma unroll
        for (int rr = 0; rr < 16; rr++) {
            const float4 h = reinterpret_cast<const float4*>(rows[rr])[k];
            acc[rr] += w.x * h.x + w.y * h.y + w.z * h.z + w.w * h.w;
        }
    }
#pragma unroll
    for (int rr = 0; rr < 16; rr++)
        g_X[(t0 + rr) * TMP + j] = acc[rr];
}

// ---------------------------------------------------------------------------
// Phase 1b: C[e][j] = dot(emb_table[e, :], W1[j, 256:272])
// ---------------------------------------------------------------------------
__global__ void __launch_bounds__(128) c_kernel(const float* __restrict__ emb,
                                                const float* __restrict__ W1) {
    __shared__ __align__(16) float e[EMB];
    const int ei = blockIdx.x;
    const int j  = threadIdx.x;
    if (j < EMB) e[j] = emb[ei * EMB + j];
    __syncthreads();

    const float4* w4 = reinterpret_cast<const float4*>(W1 + j * (HID + EMB) + HID);
    const float4* e4 = reinterpret_cast<const float4*>(e);
    float a = 0.f;
#pragma unroll
    for (int k = 0; k < EMB / 4; k++) {
        float4 w = w4[k];
        float4 h = e4[k];
        a += w.x * h.x + w.y * h.y + w.z * h.z + w.w * h.w;
    }
    g_C[ei * TMP + j] = a;
}

// ---------------------------------------------------------------------------
// Phase 1c: transpose W2 [EVD, TMP] -> g_W2T [TMP, EVD] (32x32 smem tiles)
// ---------------------------------------------------------------------------
__global__ void __launch_bounds__(256) w2t_kernel(const float* __restrict__ W2) {
    __shared__ float tile[32][33];
    const int cb = blockIdx.x * 32;   // col (EVD) base
    const int kb = blockIdx.y * 32;   // k (TMP) base
    const int tx = threadIdx.x & 31;
    const int ty = threadIdx.x >> 5;  // 0..7
#pragma unroll
    for (int i = 0; i < 4; i++) {
        const int c = cb + ty + i * 8;
        tile[ty + i * 8][tx] = W2[(size_t)c * TMP + kb + tx];
    }
    __syncthreads();
#pragma unroll
    for (int i = 0; i < 4; i++) {
        const int k = kb + ty + i * 8;
        g_W2T[(size_t)k * EVD + cb + tx] = tile[tx][ty + i * 8];
    }
}

// ---------------------------------------------------------------------------
// One decode step, parity fixed at compile time (unrolled x2 in the caller).
// ---------------------------------------------------------------------------
struct SeqCtx {
    float* sh_h;
    unsigned long long* cand;   // this parity's 64-slot buffer
    unsigned lm, rc, rm;        // this parity's local mbar / remote cand / remote mbar
};

__device__ __forceinline__ int seq_step(
    const SeqCtx& cx, int t, int idx, float xv, float& xn,
    const unsigned long long* __restrict__ w, float bias,
    int tid, int lane, unsigned irow, bool is_pusher, bool is_writer, int ph) {

    // h = leaky(X[t] + C[idx])  (all 128 threads, one coalesced 512B load)
    {
        float v = xv + g_C[idx * TMP + tid];
        cx.sh_h[tid] = (v > 0.f) ? v : NEG_SLOPE * v;
    }
    // prefetch next X row (g_X padded, so no bounds check needed)
    xn = g_X[(t + 1) * TMP + tid];
    __syncthreads();   // h visible to all warps (the ONLY per-step barrier)

    // post expectation for this step's 64 incoming candidates (512 bytes)
    if (tid == 0) {
        asm volatile("mbarrier.arrive.expect_tx.shared.b64 _, [%0], %1;"
                     :: "r"(cx.lm), "r"(64 * 8) : "memory");
    }

    // GEMV: logit = W2[r] . h + b2[r]  (packed f32x2, 4 independent chains)
    const ulonglong2* h16 = reinterpret_cast<const ulonglong2*>(cx.sh_h);
    unsigned long long a0 = 0ull, a1 = 0ull, a2 = 0ull, a3 = 0ull;
#pragma unroll
    for (int k = 0; k < 32; k += 2) {
        ulonglong2 hA = h16[k];
        ulonglong2 hB = h16[k + 1];
        a0 = fma2(w[2 * k + 0], hA.x, a0);
        a1 = fma2(w[2 * k + 1], hA.y, a1);
        a2 = fma2(w[2 * k + 2], hB.x, a2);
        a3 = fma2(w[2 * k + 3], hB.y, a3);
    }
    float2 f0 = unpack2(a0), f1 = unpack2(a1), f2v = unpack2(a2), f3 = unpack2(a3);
    const float acc = bias + (((f0.x + f0.y) + (f1.x + f1.y)) +
                              ((f2v.x + f2v.y) + (f3.x + f3.y)));

    // warp argmax via dual REDUX: max key, then max inverted-row among key-winners
    unsigned key = __float_as_uint(acc);
    key ^= (key & 0x80000000u) ? 0xFFFFFFFFu : 0x80000000u;
    const unsigned kmax  = __reduce_max_sync(0xFFFFFFFFu, key);
    const unsigned wirow = __reduce_max_sync(0xFFFFFFFFu, (key == kmax) ? irow : 0u);
    const unsigned long long v = ((unsigned long long)kmax << 32) | wirow;

    // every warp pushes its candidate to ALL 16 ranks (precomputed addrs)
    if (is_pusher) {
        asm volatile(
            "st.async.weak.shared::cluster.mbarrier::complete_tx::bytes.b64 [%0], %1, [%2];"
            :: "r"(cx.rc), "l"(v), "r"(cx.rm) : "memory");
    }

    // every warp waits the LOCAL mbarrier (cta-scope acquire, HW sleep)
    asm volatile(
        "{\n\t.reg .pred P1;\n\t"
        "LW%=:\n\t"
        "mbarrier.try_wait.parity.acquire.cta.shared::cta.b64 P1, [%0], %1, 0x989680;\n\t"
        "@P1 bra.uni LD%=;\n\t"
        "bra.uni LW%=;\n\t"
        "LD%=:\n\t}"
        :: "r"(cx.lm), "r"(ph) : "memory");

    // every warp reduces the 64 candidates: one LDS.128 + local max + dual REDUX
    int nidx;
    {
        const ulonglong2 cc = reinterpret_cast<const ulonglong2*>(cx.cand)[lane];
        const unsigned long long lv = (cc.x > cc.y) ? cc.x : cc.y;
        const unsigned hi = (unsigned)(lv >> 32);
        const unsigned lo = (unsigned)lv;
        const unsigned hmax = __reduce_max_sync(0xFFFFFFFFu, hi);
        const unsigned lmax = __reduce_max_sync(0xFFFFFFFFu, (hi == hmax) ? lo : 0u);
        nidx = 2047 - (int)lmax;
    }
    if (is_writer) g_idx[t] = nidx;
    return nidx;
    // NOTE: no tail barrier. mbar completion implies every warp's GEMV
    // reads of sh_h finished (their st.async is data-dependent on them).
}

// ---------------------------------------------------------------------------
// Phase 2: sequential greedy decode. Cluster of 16 CTAs x 128 threads.
// R14 loop body, unrolled x2 with parity constants hardwired per half
// (removes per-step SELs for lm/rc/rm and the parity computation).
// ---------------------------------------------------------------------------
__global__ void __cluster_dims__(NCTA, 1, 1) __launch_bounds__(NTHR, 1)
seq_kernel(const float* __restrict__ W2, const float* __restrict__ b2,
           const int* __restrict__ initp) {
    __shared__ __align__(16) float sh_h[TMP];
    __shared__ __align__(16) unsigned long long cand[2][64];  // [parity][src_rank*4+src_wid]
    __shared__ __align__(8) unsigned long long mbar[2];       // double-buffered mbarriers

    unsigned rank;
    asm("mov.u32 %0, %%cluster_ctarank;" : "=r"(rank));
    const int tid  = threadIdx.x;
    const int lane = tid & 31;
    const int wid  = tid >> 5;
    const int r    = (int)rank * NTHR + tid;   // this thread's logit row
    const unsigned irow = 2047u - (unsigned)r; // inverted row (max => lowest row)
    const bool is_writer = (rank == 0) && (tid == 0);
    const bool is_pusher = (lane < NCTA);

    // Pin W2 row as 64 packed f32x2 registers + bias.
    unsigned long long w[TMP / 2];
    const unsigned long long* wp =
        reinterpret_cast<const unsigned long long*>(W2 + (size_t)r * TMP);
#pragma unroll
    for (int k = 0; k < TMP / 2; k++) w[k] = wp[k];
    const float bias = b2[r];

    // Precompute all exchange addresses (both parities) outside the loop.
    const unsigned lm0 = (unsigned)__cvta_generic_to_shared(&mbar[0]);
    const unsigned lm1 = (unsigned)__cvta_generic_to_shared(&mbar[1]);
    unsigned rc0 = 0, rc1 = 0, rm0 = 0, rm1 = 0;
    {
        const unsigned lc0 = (unsigned)__cvta_generic_to_shared(&cand[0][rank * 4 + wid]);
        const unsigned lc1 = (unsigned)__cvta_generic_to_shared(&cand[1][rank * 4 + wid]);
        const unsigned dst = (unsigned)lane & (NCTA - 1);  // valid for lanes 0-15
        asm("mapa.shared::cluster.u32 %0, %1, %2;" : "=r"(rc0) : "r"(lc0), "r"(dst));
        asm("mapa.shared::cluster.u32 %0, %1, %2;" : "=r"(rc1) : "r"(lc1), "r"(dst));
        asm("mapa.shared::cluster.u32 %0, %1, %2;" : "=r"(rm0) : "r"(lm0), "r"(dst));
        asm("mapa.shared::cluster.u32 %0, %1, %2;" : "=r"(rm1) : "r"(lm1), "r"(dst));
    }

    if (tid == 0) {
        // arrive count 1: tid0's arrive.expect_tx each phase; completion gated on tx bytes.
        asm volatile("mbarrier.init.shared.b64 [%0], %1;" :: "r"(lm0), "r"(1) : "memory");
        asm volatile("mbarrier.init.shared.b64 [%0], %1;" :: "r"(lm1), "r"(1) : "memory");
        asm volatile("fence.mbarrier_init.release.cluster;" ::: "memory");
    }
    __syncthreads();
    asm volatile("barrier.cluster.arrive.aligned;" ::: "memory");
    asm volatile("barrier.cluster.wait.aligned;" ::: "memory");

    const SeqCtx cx0{sh_h, cand[0], lm0, rc0, rm0};
    const SeqCtx cx1{sh_h, cand[1], lm1, rc1, rm1};

    int idx = *initp;
    float xv = g_X[tid];

    for (int t = 0; t < T_LEN; t += 2) {
        const int ph = (t >> 1) & 1;
        float xn;
        idx = seq_step(cx0, t,     idx, xv, xn, w, bias, tid, lane, irow,
                       is_pusher, is_writer, ph);
        xv = xn;
        idx = seq_step(cx1, t + 1, idx, xv, xn, w, bias, tid, lane, irow,
                       is_pusher, is_writer, ph);
        xv = xn;
    }
}

// ---------------------------------------------------------------------------
// Phase 3: recompute logits for all t from W2T (coalesced: 4 consecutive
// cols per thread), 16 rows per CTA, log_softmax, write all three outputs:
// [T*2048 log_probs | T*16 emb | T index-as-float]. Runs AFTER seq.
// ---------------------------------------------------------------------------
__global__ void __launch_bounds__(512) out_kernel(const float* __restrict__ b2,
                                                  const float* __restrict__ emb,
                                                  const int* __restrict__ initp,
                                                  float* __restrict__ out) {
    __shared__ __align__(16) unsigned long long sh_hd[16][TMP];  // duplicated h pairs, 16KB
    __shared__ float red[16];
    const int t0  = blockIdx.x * 16;
    const int tid = threadIdx.x;
    const int lane = tid & 31;
    const int wid  = tid >> 5;

    // rebuild h rows exactly as in seq_kernel; store duplicated (v,v) pairs
    for (int q = tid; q < 16 * TMP; q += 512) {
        const int rr = q >> 7, j = q & 127;
        const int t = t0 + rr;
        const int in_idx = (t == 0) ? *initp : g_idx[t - 1];
        float v = g_X[t * TMP + j] + g_C[in_idx * TMP + j];
        v = (v > 0.f) ? v : NEG_SLOPE * v;
        sh_hd[rr][j] = dup2(v);
    }
    __syncthreads();

    // this thread's 4 consecutive cols: c = 4*tid .. 4*tid+3
    unsigned long long acc[16][2];
#pragma unroll
    for (int rr = 0; rr < 16; rr++) { acc[rr][0] = 0ull; acc[rr][1] = 0ull; }

    const ulonglong2* Wt = reinterpret_cast<const ulonglong2*>(g_W2T);
#pragma unroll 2
    for (int k = 0; k < TMP; k++) {
        const ulonglong2 wv = Wt[(size_t)k * (EVD / 4) + tid];  // 4 cols, coalesced
#pragma unroll
        for (int rr = 0; rr < 16; rr++) {
            const unsigned long long hd = sh_hd[rr][k];  // LDS.64 broadcast
            acc[rr][0] = fma2(wv.x, hd, acc[rr][0]);
            acc[rr][1] = fma2(wv.y, hd, acc[rr][1]);
        }
    }

    // add bias; unpack to scalars
    const ulonglong2 bv = reinterpret_cast<const ulonglong2*>(b2)[tid];
    const float2 b01 = unpack2(bv.x), b23 = unpack2(bv.y);
    float logit[16][4];
#pragma unroll
    for (int rr = 0; rr < 16; rr++) {
        const float2 p0 = unpack2(acc[rr][0]);
        const float2 p1 = unpack2(acc[rr][1]);
        logit[rr][0] = p0.x + b01.x;
        logit[rr][1] = p0.y + b01.y;
        logit[rr][2] = p1.x + b23.x;
        logit[rr][3] = p1.y + b23.y;
    }

    // log_softmax per row, then write (STG.128 of 4 consecutive cols)
    for (int rr = 0; rr < 16; rr++) {
        float m = fmaxf(fmaxf(logit[rr][0], logit[rr][1]),
                        fmaxf(logit[rr][2], logit[rr][3]));
#pragma unroll
        for (int o = 16; o > 0; o >>= 1) m = fmaxf(m, __shfl_xor_sync(0xFFFFFFFFu, m, o));
        if (lane == 0) red[wid] = m;
        __syncthreads();
        float M = red[0];
#pragma unroll
        for (int i = 1; i < 16; i++) M = fmaxf(M, red[i]);
        __syncthreads();

        float s = 0.f;
#pragma unroll
        for (int cj = 0; cj < 4; cj++) s += __expf(logit[rr][cj] - M);
#pragma unroll
        for (int o = 16; o > 0; o >>= 1) s += __shfl_xor_sync(0xFFFFFFFFu, s, o);
        if (lane == 0) red[wid] = s;
        __syncthreads();
        float S = 0.f;
#pragma unroll
        for (int i = 0; i < 16; i++) S += red[i];
        __syncthreads();

        const float lse = M + __logf(S);
        const int t = t0 + rr;
        float4 o4;
        o4.x = logit[rr][0] - lse;
        o4.y = logit[rr][1] - lse;
        o4.z = logit[rr][2] - lse;
        o4.w = logit[rr][3] - lse;
        *reinterpret_cast<float4*>(&out[(size_t)t * EVD + 4 * tid]) = o4;
    }

    // ner_emb and ner_index outputs
    float* out_emb = out + (size_t)T_LEN * EVD;
    float* out_idx = out_emb + (size_t)T_LEN * EMB;
    if (tid < 16 * EMB) {
        const int rr = tid >> 4, j = tid & 15;
        const int t = t0 + rr;
        out_emb[t * EMB + j] = emb[g_idx[t] * EMB + j];
    }
    if (tid < 16) {
        const int t = t0 + tid;
        out_idx[t] = (float)g_idx[t];
    }
}

// ---------------------------------------------------------------------------
extern "C" void kernel_launch(void* const* d_in, const int* in_sizes, int n_in,
                              void* d_out, int out_size) {
    const float* bilstm = (const float*)d_in[0];
    const float* emb    = (const float*)d_in[1];
    const float* W1     = (const float*)d_in[2];
    const float* b1     = (const float*)d_in[3];
    const float* W2     = (const float*)d_in[4];
    const float* b2     = (const float*)d_in[5];
    const int*   init   = (const int*)d_in[6];
    float* out = (float*)d_out;

    // Allow the 16-CTA (non-portable) cluster. Host-side attribute set:
    // executes immediately, not a stream op -> graph-capture safe, idempotent.
    cudaFuncSetAttribute((const void*)seq_kernel,
                         cudaFuncAttributeNonPortableClusterSizeAllowed, 1);

    x_kernel<<<T_LEN / 16, 128>>>(bilstm, W1, b1);
    c_kernel<<<EVD, 128>>>(emb, W1);
    {
        dim3 g(EVD / 32, TMP / 32);
        w2t_kernel<<<g, 256>>>(W2);
    }
    seq_kernel<<<NCTA, NTHR>>>(W2, b2, init);
    out_kernel<<<T_LEN / 16, 512>>>(b2, emb, init, out);
}

// round 16
// speedup vs baseline: 1.1003x; 1.1003x over previous
#include <cuda_runtime.h>
#include <cstdint>

#define T_LEN 16384
#define HID   256
#define EMB   16
#define TMP   128
#define EVD   2048
#define NCTA  16          // 16-CTA cluster (non-portable size, enabled at launch)
#define NTHR  128         // threads per CTA; NCTA*NTHR = 2048 = one thread per logit row
#define NEG_SLOPE 0.01f

// Scratch (static device globals — no allocation at runtime)
__device__ float g_X[(T_LEN + 1) * TMP]; // bilstm part of layer-1 preactivation (+1 pad row)
__device__ float g_C[EVD * TMP];         // 1 MB: event-embedding part of layer-1 preactivation
__device__ float g_W2T[TMP * EVD];       // 1 MB: W2 transposed -> [k][col]
__device__ int   g_idx[T_LEN];           // argmax index emitted at each step

// Packed fp32x2 FMA (sm_100+): d = a*b + c elementwise on two packed floats.
__device__ __forceinline__ unsigned long long fma2(unsigned long long a,
                                                   unsigned long long b,
                                                   unsigned long long c) {
    unsigned long long d;
    asm("fma.rn.f32x2 %0, %1, %2, %3;" : "=l"(d) : "l"(a), "l"(b), "l"(c));
    return d;
}
__device__ __forceinline__ float2 unpack2(unsigned long long v) {
    float2 r;
    asm("mov.b64 {%0, %1}, %2;" : "=f"(r.x), "=f"(r.y) : "l"(v));
    return r;
}
__device__ __forceinline__ unsigned long long dup2(float v) {
    unsigned long long d;
    asm("mov.b64 %0, {%1, %1};" : "=l"(d) : "f"(v));
    return d;
}

// ---------------------------------------------------------------------------
// Phase 1a: X[t][j] for 16 timesteps per CTA (W1 row read once per 16 rows).
// ---------------------------------------------------------------------------
__global__ void __launch_bounds__(128) x_kernel(const float* __restrict__ bilstm,
                                                const float* __restrict__ W1,
                                                const float* __restrict__ b1) {
    __shared__ __align__(16) float rows[16][HID];
    const int t0 = blockIdx.x * 16;
    const int j  = threadIdx.x;

    for (int q = j; q < 16 * HID; q += 128) {
        rows[q >> 8][q & 255] = bilstm[t0 * HID + q];
    }
    __syncthreads();

    const float4* w4 = reinterpret_cast<const float4*>(W1 + j * (HID + EMB));
    float acc[16];
    const float bb = b1[j];
#pragma unroll
    for (int rr = 0; rr < 16; rr++) acc[rr] = bb;

#pragma unroll 4
    for (int k = 0; k < HID / 4; k++) {
        const float4 w = w4[k];
#pragma unroll
        for (int rr = 0; rr < 16; rr++) {
            const float4 h = reinterpret_cast<const float4*>(rows[rr])[k];
            acc[rr] += w.x * h.x + w.y * h.y + w.z * h.z + w.w * h.w;
        }
    }
#pragma unroll
    for (int rr = 0; rr < 16; rr++)
        g_X[(t0 + rr) * TMP + j] = acc[rr];
}

// ---------------------------------------------------------------------------
// Phase 1b: C[e][j] = dot(emb_table[e, :], W1[j, 256:272])
// ---------------------------------------------------------------------------
__global__ void __launch_bounds__(128) c_kernel(const float* __restrict__ emb,
                                                const float* __restrict__ W1) {
    __shared__ __align__(16) float e[EMB];
    const int ei = blockIdx.x;
    const int j  = threadIdx.x;
    if (j < EMB) e[j] = emb[ei * EMB + j];
    __syncthreads();

    const float4* w4 = reinterpret_cast<const float4*>(W1 + j * (HID + EMB) + HID);
    const float4* e4 = reinterpret_cast<const float4*>(e);
    float a = 0.f;
#pragma unroll
    for (int k = 0; k < EMB / 4; k++) {
        float4 w = w4[k];
        float4 h = e4[k];
        a += w.x * h.x + w.y * h.y + w.z * h.z + w.w * h.w;
    }
    g_C[ei * TMP + j] = a;
}

// ---------------------------------------------------------------------------
// Phase 1c: transpose W2 [EVD, TMP] -> g_W2T [TMP, EVD] (32x32 smem tiles)
// ---------------------------------------------------------------------------
__global__ void __launch_bounds__(256) w2t_kernel(const float* __restrict__ W2) {
    __shared__ float tile[32][33];
    const int cb = blockIdx.x * 32;   // col (EVD) base
    const int kb = blockIdx.y * 32;   // k (TMP) base
    const int tx = threadIdx.x & 31;
    const int ty = threadIdx.x >> 5;  // 0..7
#pragma unroll
    for (int i = 0; i < 4; i++) {
        const int c = cb + ty + i * 8;
        tile[ty + i * 8][tx] = W2[(size_t)c * TMP + kb + tx];
    }
    __syncthreads();
#pragma unroll
    for (int i = 0; i < 4; i++) {
        const int k = kb + ty + i * 8;
        g_W2T[(size_t)k * EVD + cb + tx] = tile[tx][ty + i * 8];
    }
}

// ---------------------------------------------------------------------------
// Phase 2: sequential greedy decode. Cluster of 16 CTAs x 128 threads
// (1 warp/SMSP -> minimal GEMV issue). Byte-exact R10/R12/R14 loop body —
// the measured equilibrium. Shared h built by all 128 threads + ONE
// __syncthreads; every warp pushes its candidate to all 16 ranks (single
// st.async each, precomputed mapa addresses); every warp waits the local
// mbarrier and reduces the 64 slots itself. No branches, no speculation,
// no unrolling, no concurrent work (each measured 0.25-8ms WORSE).
// ---------------------------------------------------------------------------
__global__ void __cluster_dims__(NCTA, 1, 1) __launch_bounds__(NTHR, 1)
seq_kernel(const float* __restrict__ W2, const float* __restrict__ b2,
           const int* __restrict__ initp) {
    __shared__ __align__(16) float sh_h[TMP];
    __shared__ __align__(16) unsigned long long cand[2][64];  // [parity][src_rank*4+src_wid]
    __shared__ __align__(8) unsigned long long mbar[2];       // double-buffered mbarriers

    unsigned rank;
    asm("mov.u32 %0, %%cluster_ctarank;" : "=r"(rank));
    const int tid  = threadIdx.x;
    const int lane = tid & 31;
    const int wid  = tid >> 5;
    const int r    = (int)rank * NTHR + tid;   // this thread's logit row
    const unsigned irow = 2047u - (unsigned)r; // inverted row (max => lowest row)
    const bool is_writer = (rank == 0) && (tid == 0);
    const bool is_pusher = (lane < NCTA);

    // Pin W2 row as 64 packed f32x2 registers + bias.
    unsigned long long w[TMP / 2];
    const unsigned long long* wp =
        reinterpret_cast<const unsigned long long*>(W2 + (size_t)r * TMP);
#pragma unroll
    for (int k = 0; k < TMP / 2; k++) w[k] = wp[k];
    const float bias = b2[r];

    // Precompute all exchange addresses (both parities) outside the loop.
    const unsigned lm0 = (unsigned)__cvta_generic_to_shared(&mbar[0]);
    const unsigned lm1 = (unsigned)__cvta_generic_to_shared(&mbar[1]);
    unsigned rc0 = 0, rc1 = 0, rm0 = 0, rm1 = 0;
    {
        const unsigned lc0 = (unsigned)__cvta_generic_to_shared(&cand[0][rank * 4 + wid]);
        const unsigned lc1 = (unsigned)__cvta_generic_to_shared(&cand[1][rank * 4 + wid]);
        const unsigned dst = (unsigned)lane & (NCTA - 1);  // valid for lanes 0-15
        asm("mapa.shared::cluster.u32 %0, %1, %2;" : "=r"(rc0) : "r"(lc0), "r"(dst));
        asm("mapa.shared::cluster.u32 %0, %1, %2;" : "=r"(rc1) : "r"(lc1), "r"(dst));
        asm("mapa.shared::cluster.u32 %0, %1, %2;" : "=r"(rm0) : "r"(lm0), "r"(dst));
        asm("mapa.shared::cluster.u32 %0, %1, %2;" : "=r"(rm1) : "r"(lm1), "r"(dst));
    }

    if (tid == 0) {
        // arrive count 1: tid0's arrive.expect_tx each phase; completion gated on tx bytes.
        asm volatile("mbarrier.init.shared.b64 [%0], %1;" :: "r"(lm0), "r"(1) : "memory");
        asm volatile("mbarrier.init.shared.b64 [%0], %1;" :: "r"(lm1), "r"(1) : "memory");
        asm volatile("fence.mbarrier_init.release.cluster;" ::: "memory");
    }
    __syncthreads();
    asm volatile("barrier.cluster.arrive.aligned;" ::: "memory");
    asm volatile("barrier.cluster.wait.aligned;" ::: "memory");

    int idx = *initp;
    float xv = g_X[tid];

    for (int t = 0; t < T_LEN; t++) {
        const int p  = t & 1;
        const int ph = (t >> 1) & 1;
        const unsigned lm = p ? lm1 : lm0;

        // h = leaky(X[t] + C[idx])  (all 128 threads, one coalesced 512B load)
        {
            float v = xv + g_C[idx * TMP + tid];
            sh_h[tid] = (v > 0.f) ? v : NEG_SLOPE * v;
        }
        // prefetch next X row (g_X padded, so no bounds check needed)
        const float xn = g_X[(t + 1) * TMP + tid];
        __syncthreads();   // h visible to all warps (the ONLY per-step barrier)

        // post expectation for this step's 64 incoming candidates (512 bytes)
        if (tid == 0) {
            asm volatile("mbarrier.arrive.expect_tx.shared.b64 _, [%0], %1;"
                         :: "r"(lm), "r"(64 * 8) : "memory");
        }

        // GEMV: logit = W2[r] . h + b2[r]  (packed f32x2, 4 independent chains)
        const ulonglong2* h16 = reinterpret_cast<const ulonglong2*>(sh_h);
        unsigned long long a0 = 0ull, a1 = 0ull, a2 = 0ull, a3 = 0ull;
#pragma unroll
        for (int k = 0; k < 32; k += 2) {
            ulonglong2 hA = h16[k];
            ulonglong2 hB = h16[k + 1];
            a0 = fma2(w[2 * k + 0], hA.x, a0);
            a1 = fma2(w[2 * k + 1], hA.y, a1);
            a2 = fma2(w[2 * k + 2], hB.x, a2);
            a3 = fma2(w[2 * k + 3], hB.y, a3);
        }
        float2 f0 = unpack2(a0), f1 = unpack2(a1), f2v = unpack2(a2), f3 = unpack2(a3);
        const float acc = bias + (((f0.x + f0.y) + (f1.x + f1.y)) +
                                  ((f2v.x + f2v.y) + (f3.x + f3.y)));

        // warp argmax via dual REDUX: max key, then max inverted-row among key-winners
        unsigned key = __float_as_uint(acc);
        key ^= (key & 0x80000000u) ? 0xFFFFFFFFu : 0x80000000u;
        const unsigned kmax  = __reduce_max_sync(0xFFFFFFFFu, key);
        const unsigned wirow = __reduce_max_sync(0xFFFFFFFFu, (key == kmax) ? irow : 0u);
        const unsigned long long v = ((unsigned long long)kmax << 32) | wirow;

        // every warp pushes its candidate to ALL 16 ranks (precomputed addrs)
        if (is_pusher) {
            const unsigned rc = p ? rc1 : rc0;
            const unsigned rm = p ? rm1 : rm0;
            asm volatile(
                "st.async.weak.shared::cluster.mbarrier::complete_tx::bytes.b64 [%0], %1, [%2];"
                :: "r"(rc), "l"(v), "r"(rm) : "memory");
        }

        // every warp waits the LOCAL mbarrier (cta-scope acquire, HW sleep)
        asm volatile(
            "{\n\t.reg .pred P1;\n\t"
            "LW%=:\n\t"
            "mbarrier.try_wait.parity.acquire.cta.shared::cta.b64 P1, [%0], %1, 0x989680;\n\t"
            "@P1 bra.uni LD%=;\n\t"
            "bra.uni LW%=;\n\t"
            "LD%=:\n\t}"
            :: "r"(lm), "r"(ph) : "memory");

        // every warp reduces the 64 candidates: one LDS.128 + local max + dual REDUX
        {
            const ulonglong2 cc = reinterpret_cast<const ulonglong2*>(cand[p])[lane];
            const unsigned long long lv = (cc.x > cc.y) ? cc.x : cc.y;
            const unsigned hi = (unsigned)(lv >> 32);
            const unsigned lo = (unsigned)lv;
            const unsigned hmax = __reduce_max_sync(0xFFFFFFFFu, hi);
            const unsigned lmax = __reduce_max_sync(0xFFFFFFFFu, (hi == hmax) ? lo : 0u);
            idx = 2047 - (int)lmax;
        }
        if (is_writer) g_idx[t] = idx;
        xv = xn;
        // NOTE: no tail barrier. mbar completion implies every warp's GEMV
        // reads of sh_h finished (their st.async is data-dependent on them),
        // so sh_h may be safely overwritten next iteration.
    }
}

// ---------------------------------------------------------------------------
// Phase 3: recompute logits for all t from W2T (coalesced: 4 consecutive
// cols per thread), 16 rows per CTA, log_softmax, write all three outputs:
// [T*2048 log_probs | T*16 emb | T index-as-float]. Runs AFTER seq.
// ---------------------------------------------------------------------------
__global__ void __launch_bounds__(512) out_kernel(const float* __restrict__ b2,
                                                  const float* __restrict__ emb,
                                                  const int* __restrict__ initp,
                                                  float* __restrict__ out) {
    __shared__ __align__(16) unsigned long long sh_hd[16][TMP];  // duplicated h pairs, 16KB
    __shared__ float red[16];
    const int t0  = blockIdx.x * 16;
    const int tid = threadIdx.x;
    const int lane = tid & 31;
    const int wid  = tid >> 5;

    // rebuild h rows exactly as in seq_kernel; store duplicated (v,v) pairs
    for (int q = tid; q < 16 * TMP; q += 512) {
        const int rr = q >> 7, j = q & 127;
        const int t = t0 + rr;
        const int in_idx = (t == 0) ? *initp : g_idx[t - 1];
        float v = g_X[t * TMP + j] + g_C[in_idx * TMP + j];
        v = (v > 0.f) ? v : NEG_SLOPE * v;
        sh_hd[rr][j] = dup2(v);
    }
    __syncthreads();

    // this thread's 4 consecutive cols: c = 4*tid .. 4*tid+3
    unsigned long long acc[16][2];
#pragma unroll
    for (int rr = 0; rr < 16; rr++) { acc[rr][0] = 0ull; acc[rr][1] = 0ull; }

    const ulonglong2* Wt = reinterpret_cast<const ulonglong2*>(g_W2T);
#pragma unroll 2
    for (int k = 0; k < TMP; k++) {
        const ulonglong2 wv = Wt[(size_t)k * (EVD / 4) + tid];  // 4 cols, coalesced
#pragma unroll
        for (int rr = 0; rr < 16; rr++) {
            const unsigned long long hd = sh_hd[rr][k];  // LDS.64 broadcast
            acc[rr][0] = fma2(wv.x, hd, acc[rr][0]);
            acc[rr][1] = fma2(wv.y, hd, acc[rr][1]);
        }
    }

    // add bias; unpack to scalars
    const ulonglong2 bv = reinterpret_cast<const ulonglong2*>(b2)[tid];
    const float2 b01 = unpack2(bv.x), b23 = unpack2(bv.y);
    float logit[16][4];
#pragma unroll
    for (int rr = 0; rr < 16; rr++) {
        const float2 p0 = unpack2(acc[rr][0]);
        const float2 p1 = unpack2(acc[rr][1]);
        logit[rr][0] = p0.x + b01.x;
        logit[rr][1] = p0.y + b01.y;
        logit[rr][2] = p1.x + b23.x;
        logit[rr][3] = p1.y + b23.y;
    }

    // log_softmax per row, then write (STG.128 of 4 consecutive cols)
    for (int rr = 0; rr < 16; rr++) {
        float m = fmaxf(fmaxf(logit[rr][0], logit[rr][1]),
                        fmaxf(logit[rr][2], logit[rr][3]));
#pragma unroll
        for (int o = 16; o > 0; o >>= 1) m = fmaxf(m, __shfl_xor_sync(0xFFFFFFFFu, m, o));
        if (lane == 0) red[wid] = m;
        __syncthreads();
        float M = red[0];
#pragma unroll
        for (int i = 1; i < 16; i++) M = fmaxf(M, red[i]);
        __syncthreads();

        float s = 0.f;
#pragma unroll
        for (int cj = 0; cj < 4; cj++) s += __expf(logit[rr][cj] - M);
#pragma unroll
        for (int o = 16; o > 0; o >>= 1) s += __shfl_xor_sync(0xFFFFFFFFu, s, o);
        if (lane == 0) red[wid] = s;
        __syncthreads();
        float S = 0.f;
#pragma unroll
        for (int i = 0; i < 16; i++) S += red[i];
        __syncthreads();

        const float lse = M + __logf(S);
        const int t = t0 + rr;
        float4 o4;
        o4.x = logit[rr][0] - lse;
        o4.y = logit[rr][1] - lse;
        o4.z = logit[rr][2] - lse;
        o4.w = logit[rr][3] - lse;
        *reinterpret_cast<float4*>(&out[(size_t)t * EVD + 4 * tid]) = o4;
    }

    // ner_emb and ner_index outputs
    float* out_emb = out + (size_t)T_LEN * EVD;
    float* out_idx = out_emb + (size_t)T_LEN * EMB;
    if (tid < 16 * EMB) {
        const int rr = tid >> 4, j = tid & 15;
        const int t = t0 + rr;
        out_emb[t * EMB + j] = emb[g_idx[t] * EMB + j];
    }
    if (tid < 16) {
        const int t = t0 + tid;
        out_idx[t] = (float)g_idx[t];
    }
}

// ---------------------------------------------------------------------------
extern "C" void kernel_launch(void* const* d_in, const int* in_sizes, int n_in,
                              void* d_out, int out_size) {
    const float* bilstm = (const float*)d_in[0];
    const float* emb    = (const float*)d_in[1];
    const float* W1     = (const float*)d_in[2];
    const float* b1     = (const float*)d_in[3];
    const float* W2     = (const float*)d_in[4];
    const float* b2     = (const float*)d_in[5];
    const int*   init   = (const int*)d_in[6];
    float* out = (float*)d_out;

    // Allow the 16-CTA (non-portable) cluster. Host-side attribute set:
    // executes immediately, not a stream op -> graph-capture safe, idempotent.
    cudaFuncSetAttribute((const void*)seq_kernel,
                         cudaFuncAttributeNonPortableClusterSizeAllowed, 1);

    x_kernel<<<T_LEN / 16, 128>>>(bilstm, W1, b1);
    c_kernel<<<EVD, 128>>>(emb, W1);
    {
        dim3 g(EVD / 32, TMP / 32);
        w2t_kernel<<<g, 256>>>(W2);
    }
    seq_kernel<<<NCTA, NTHR>>>(W2, b2, init);
    out_kernel<<<T_LEN / 16, 512>>>(b2, emb, init, out);
}

// round 17
// speedup vs baseline: 1.1030x; 1.0024x over previous
#include <cuda_runtime.h>
#include <cstdint>

#define T_LEN 16384
#define HID   256
#define EMB   16
#define TMP   128
#define EVD   2048
#define NCTA  16          // 16-CTA cluster (non-portable size, enabled at launch)
#define NTHR  128         // threads per CTA; NCTA*NTHR = 2048 = one thread per logit row
#define NEG_SLOPE 0.01f

// Scratch (static device globals — no allocation at runtime)
__device__ float g_X[(T_LEN + 1) * TMP]; // bilstm part of layer-1 preactivation (+1 pad row)
__device__ float g_C[EVD * TMP];         // 1 MB: event-embedding part of layer-1 preactivation
__device__ float g_W2T[TMP * EVD];       // 1 MB: W2 transposed -> [k][col]
__device__ int   g_idx[T_LEN];           // argmax index emitted at each step

// Packed fp32x2 FMA (sm_100+): d = a*b + c elementwise on two packed floats.
__device__ __forceinline__ unsigned long long fma2(unsigned long long a,
                                                   unsigned long long b,
                                                   unsigned long long c) {
    unsigned long long d;
    asm("fma.rn.f32x2 %0, %1, %2, %3;" : "=l"(d) : "l"(a), "l"(b), "l"(c));
    return d;
}
__device__ __forceinline__ float2 unpack2(unsigned long long v) {
    float2 r;
    asm("mov.b64 {%0, %1}, %2;" : "=f"(r.x), "=f"(r.y) : "l"(v));
    return r;
}
__device__ __forceinline__ unsigned long long dup2(float v) {
    unsigned long long d;
    asm("mov.b64 %0, {%1, %1};" : "=l"(d) : "f"(v));
    return d;
}

// ---------------------------------------------------------------------------
// Phase 1a: X[t][j] for 16 timesteps per CTA (W1 row read once per 16 rows).
// ---------------------------------------------------------------------------
__global__ void __launch_bounds__(128) x_kernel(const float* __restrict__ bilstm,
                                                const float* __restrict__ W1,
                                                const float* __restrict__ b1) {
    __shared__ __align__(16) float rows[16][HID];
    const int t0 = blockIdx.x * 16;
    const int j  = threadIdx.x;

    for (int q = j; q < 16 * HID; q += 128) {
        rows[q >> 8][q & 255] = bilstm[t0 * HID + q];
    }
    __syncthreads();

    const float4* w4 = reinterpret_cast<const float4*>(W1 + j * (HID + EMB));
    float acc[16];
    const float bb = b1[j];
#pragma unroll
    for (int rr = 0; rr < 16; rr++) acc[rr] = bb;

#pragma unroll 4
    for (int k = 0; k < HID / 4; k++) {
        const float4 w = w4[k];
#pragma unroll
        for (int rr = 0; rr < 16; rr++) {
            const float4 h = reinterpret_cast<const float4*>(rows[rr])[k];
            acc[rr] += w.x * h.x + w.y * h.y + w.z * h.z + w.w * h.w;
        }
    }
#pragma unroll
    for (int rr = 0; rr < 16; rr++)
        g_X[(t0 + rr) * TMP + j] = acc[rr];
}

// ---------------------------------------------------------------------------
// Phase 1b: C[e][j] = dot(emb_table[e, :], W1[j, 256:272])
// ---------------------------------------------------------------------------
__global__ void __launch_bounds__(128) c_kernel(const float* __restrict__ emb,
                                                const float* __restrict__ W1) {
    __shared__ __align__(16) float e[EMB];
    const int ei = blockIdx.x;
    const int j  = threadIdx.x;
    if (j < EMB) e[j] = emb[ei * EMB + j];
    __syncthreads();

    const float4* w4 = reinterpret_cast<const float4*>(W1 + j * (HID + EMB) + HID);
    const float4* e4 = reinterpret_cast<const float4*>(e);
    float a = 0.f;
#pragma unroll
    for (int k = 0; k < EMB / 4; k++) {
        float4 w = w4[k];
        float4 h = e4[k];
        a += w.x * h.x + w.y * h.y + w.z * h.z + w.w * h.w;
    }
    g_C[ei * TMP + j] = a;
}

// ---------------------------------------------------------------------------
// Phase 1c: transpose W2 [EVD, TMP] -> g_W2T [TMP, EVD] (32x32 smem tiles)
// ---------------------------------------------------------------------------
__global__ void __launch_bounds__(256) w2t_kernel(const float* __restrict__ W2) {
    __shared__ float tile[32][33];
    const int cb = blockIdx.x * 32;   // col (EVD) base
    const int kb = blockIdx.y * 32;   // k (TMP) base
    const int tx = threadIdx.x & 31;
    const int ty = threadIdx.x >> 5;  // 0..7
#pragma unroll
    for (int i = 0; i < 4; i++) {
        const int c = cb + ty + i * 8;
        tile[ty + i * 8][tx] = W2[(size_t)c * TMP + kb + tx];
    }
    __syncthreads();
#pragma unroll
    for (int i = 0; i < 4; i++) {
        const int k = kb + ty + i * 8;
        g_W2T[(size_t)k * EVD + cb + tx] = tile[tx][ty + i * 8];
    }
}

// ---------------------------------------------------------------------------
// Phase 2: sequential greedy decode. Cluster of 16 CTAs x 128 threads
// (1 warp/SMSP -> minimal GEMV issue). Byte-exact measured-equilibrium loop
// body (R10/R12/R14/R16: 9874-9913us across four runs). Shared h built by
// all 128 threads + ONE __syncthreads; every warp pushes its candidate to
// all 16 ranks (single st.async each, precomputed mapa addresses); every
// warp waits the local mbarrier and reduces the 64 slots itself. No
// branches, no speculation, no unrolling, no concurrent work (each of
// those measured 0.25-8ms WORSE across six experiment classes).
// ---------------------------------------------------------------------------
__global__ void __cluster_dims__(NCTA, 1, 1) __launch_bounds__(NTHR, 1)
seq_kernel(const float* __restrict__ W2, const float* __restrict__ b2,
           const int* __restrict__ initp) {
    __shared__ __align__(16) float sh_h[TMP];
    __shared__ __align__(16) unsigned long long cand[2][64];  // [parity][src_rank*4+src_wid]
    __shared__ __align__(8) unsigned long long mbar[2];       // double-buffered mbarriers

    unsigned rank;
    asm("mov.u32 %0, %%cluster_ctarank;" : "=r"(rank));
    const int tid  = threadIdx.x;
    const int lane = tid & 31;
    const int wid  = tid >> 5;
    const int r    = (int)rank * NTHR + tid;   // this thread's logit row
    const unsigned irow = 2047u - (unsigned)r; // inverted row (max => lowest row)
    const bool is_writer = (rank == 0) && (tid == 0);
    const bool is_pusher = (lane < NCTA);

    // Pin W2 row as 64 packed f32x2 registers + bias.
    unsigned long long w[TMP / 2];
    const unsigned long long* wp =
        reinterpret_cast<const unsigned long long*>(W2 + (size_t)r * TMP);
#pragma unroll
    for (int k = 0; k < TMP / 2; k++) w[k] = wp[k];
    const float bias = b2[r];

    // Precompute all exchange addresses (both parities) outside the loop.
    const unsigned lm0 = (unsigned)__cvta_generic_to_shared(&mbar[0]);
    const unsigned lm1 = (unsigned)__cvta_generic_to_shared(&mbar[1]);
    unsigned rc0 = 0, rc1 = 0, rm0 = 0, rm1 = 0;
    {
        const unsigned lc0 = (unsigned)__cvta_generic_to_shared(&cand[0][rank * 4 + wid]);
        const unsigned lc1 = (unsigned)__cvta_generic_to_shared(&cand[1][rank * 4 + wid]);
        const unsigned dst = (unsigned)lane & (NCTA - 1);  // valid for lanes 0-15
        asm("mapa.shared::cluster.u32 %0, %1, %2;" : "=r"(rc0) : "r"(lc0), "r"(dst));
        asm("mapa.shared::cluster.u32 %0, %1, %2;" : "=r"(rc1) : "r"(lc1), "r"(dst));
        asm("mapa.shared::cluster.u32 %0, %1, %2;" : "=r"(rm0) : "r"(lm0), "r"(dst));
        asm("mapa.shared::cluster.u32 %0, %1, %2;" : "=r"(rm1) : "r"(lm1), "r"(dst));
    }

    if (tid == 0) {
        // arrive count 1: tid0's arrive.expect_tx each phase; completion gated on tx bytes.
        asm volatile("mbarrier.init.shared.b64 [%0], %1;" :: "r"(lm0), "r"(1) : "memory");
        asm volatile("mbarrier.init.shared.b64 [%0], %1;" :: "r"(lm1), "r"(1) : "memory");
        asm volatile("fence.mbarrier_init.release.cluster;" ::: "memory");
    }
    __syncthreads();
    asm volatile("barrier.cluster.arrive.aligned;" ::: "memory");
    asm volatile("barrier.cluster.wait.aligned;" ::: "memory");

    int idx = *initp;
    float xv = g_X[tid];

    for (int t = 0; t < T_LEN; t++) {
        const int p  = t & 1;
        const int ph = (t >> 1) & 1;
        const unsigned lm = p ? lm1 : lm0;

        // h = leaky(X[t] + C[idx])  (all 128 threads, one coalesced 512B load;
        // repeat-winner rows are L1-resident from the previous step)
        {
            float v = xv + g_C[idx * TMP + tid];
            sh_h[tid] = (v > 0.f) ? v : NEG_SLOPE * v;
        }
        // prefetch next X row (g_X padded, so no bounds check needed)
        const float xn = g_X[(t + 1) * TMP + tid];
        __syncthreads();   // h visible to all warps (the ONLY per-step barrier)

        // post expectation for this step's 64 incoming candidates (512 bytes)
        if (tid == 0) {
            asm volatile("mbarrier.arrive.expect_tx.shared.b64 _, [%0], %1;"
                         :: "r"(lm), "r"(64 * 8) : "memory");
        }

        // GEMV: logit = W2[r] . h + b2[r]  (packed f32x2, 4 independent chains)
        const ulonglong2* h16 = reinterpret_cast<const ulonglong2*>(sh_h);
        unsigned long long a0 = 0ull, a1 = 0ull, a2 = 0ull, a3 = 0ull;
#pragma unroll
        for (int k = 0; k < 32; k += 2) {
            ulonglong2 hA = h16[k];
            ulonglong2 hB = h16[k + 1];
            a0 = fma2(w[2 * k + 0], hA.x, a0);
            a1 = fma2(w[2 * k + 1], hA.y, a1);
            a2 = fma2(w[2 * k + 2], hB.x, a2);
            a3 = fma2(w[2 * k + 3], hB.y, a3);
        }
        float2 f0 = unpack2(a0), f1 = unpack2(a1), f2v = unpack2(a2), f3 = unpack2(a3);
        const float acc = bias + (((f0.x + f0.y) + (f1.x + f1.y)) +
                                  ((f2v.x + f2v.y) + (f3.x + f3.y)));

        // warp argmax via dual REDUX: max key, then max inverted-row among key-winners
        unsigned key = __float_as_uint(acc);
        key ^= (key & 0x80000000u) ? 0xFFFFFFFFu : 0x80000000u;
        const unsigned kmax  = __reduce_max_sync(0xFFFFFFFFu, key);
        const unsigned wirow = __reduce_max_sync(0xFFFFFFFFu, (key == kmax) ? irow : 0u);
        const unsigned long long v = ((unsigned long long)kmax << 32) | wirow;

        // every warp pushes its candidate to ALL 16 ranks (precomputed addrs)
        if (is_pusher) {
            const unsigned rc = p ? rc1 : rc0;
            const unsigned rm = p ? rm1 : rm0;
            asm volatile(
                "st.async.weak.shared::cluster.mbarrier::complete_tx::bytes.b64 [%0], %1, [%2];"
                :: "r"(rc), "l"(v), "r"(rm) : "memory");
        }

        // every warp waits the LOCAL mbarrier (cta-scope acquire, HW sleep)
        asm volatile(
            "{\n\t.reg .pred P1;\n\t"
            "LW%=:\n\t"
            "mbarrier.try_wait.parity.acquire.cta.shared::cta.b64 P1, [%0], %1, 0x989680;\n\t"
            "@P1 bra.uni LD%=;\n\t"
            "bra.uni LW%=;\n\t"
            "LD%=:\n\t}"
            :: "r"(lm), "r"(ph) : "memory");

        // every warp reduces the 64 candidates: one LDS.128 + local max + dual REDUX
        {
            const ulonglong2 cc = reinterpret_cast<const ulonglong2*>(cand[p])[lane];
            const unsigned long long lv = (cc.x > cc.y) ? cc.x : cc.y;
            const unsigned hi = (unsigned)(lv >> 32);
            const unsigned lo = (unsigned)lv;
            const unsigned hmax = __reduce_max_sync(0xFFFFFFFFu, hi);
            const unsigned lmax = __reduce_max_sync(0xFFFFFFFFu, (hi == hmax) ? lo : 0u);
            idx = 2047 - (int)lmax;
        }
        if (is_writer) g_idx[t] = idx;
        xv = xn;
        // NOTE: no tail barrier. mbar completion implies every warp's GEMV
        // reads of sh_h finished (their st.async is data-dependent on them),
        // so sh_h may be safely overwritten next iteration.
    }
}

// ---------------------------------------------------------------------------
// Phase 3: recompute logits for all t from W2T (coalesced: 4 consecutive
// cols per thread), 16 rows per CTA, log_softmax, write all three outputs:
// [T*2048 log_probs | T*16 emb | T index-as-float]. Runs AFTER seq.
// ---------------------------------------------------------------------------
__global__ void __launch_bounds__(512) out_kernel(const float* __restrict__ b2,
                                                  const float* __restrict__ emb,
                                                  const int* __restrict__ initp,
                                                  float* __restrict__ out) {
    __shared__ __align__(16) unsigned long long sh_hd[16][TMP];  // duplicated h pairs, 16KB
    __shared__ float red[16];
    const int t0  = blockIdx.x * 16;
    const int tid = threadIdx.x;
    const int lane = tid & 31;
    const int wid  = tid >> 5;

    // rebuild h rows exactly as in seq_kernel; store duplicated (v,v) pairs
    for (int q = tid; q < 16 * TMP; q += 512) {
        const int rr = q >> 7, j = q & 127;
        const int t = t0 + rr;
        const int in_idx = (t == 0) ? *initp : g_idx[t - 1];
        float v = g_X[t * TMP + j] + g_C[in_idx * TMP + j];
        v = (v > 0.f) ? v : NEG_SLOPE * v;
        sh_hd[rr][j] = dup2(v);
    }
    __syncthreads();

    // this thread's 4 consecutive cols: c = 4*tid .. 4*tid+3
    unsigned long long acc[16][2];
#pragma unroll
    for (int rr = 0; rr < 16; rr++) { acc[rr][0] = 0ull; acc[rr][1] = 0ull; }

    const ulonglong2* Wt = reinterpret_cast<const ulonglong2*>(g_W2T);
#pragma unroll 2
    for (int k = 0; k < TMP; k++) {
        const ulonglong2 wv = Wt[(size_t)k * (EVD / 4) + tid];  // 4 cols, coalesced
#pragma unroll
        for (int rr = 0; rr < 16; rr++) {
            const unsigned long long hd = sh_hd[rr][k];  // LDS.64 broadcast
            acc[rr][0] = fma2(wv.x, hd, acc[rr][0]);
            acc[rr][1] = fma2(wv.y, hd, acc[rr][1]);
        }
    }

    // add bias; unpack to scalars
    const ulonglong2 bv = reinterpret_cast<const ulonglong2*>(b2)[tid];
    const float2 b01 = unpack2(bv.x), b23 = unpack2(bv.y);
    float logit[16][4];
#pragma unroll
    for (int rr = 0; rr < 16; rr++) {
        const float2 p0 = unpack2(acc[rr][0]);
        const float2 p1 = unpack2(acc[rr][1]);
        logit[rr][0] = p0.x + b01.x;
        logit[rr][1] = p0.y + b01.y;
        logit[rr][2] = p1.x + b23.x;
        logit[rr][3] = p1.y + b23.y;
    }

    // log_softmax per row, then write (STG.128 of 4 consecutive cols)
    for (int rr = 0; rr < 16; rr++) {
        float m = fmaxf(fmaxf(logit[rr][0], logit[rr][1]),
                        fmaxf(logit[rr][2], logit[rr][3]));
#pragma unroll
        for (int o = 16; o > 0; o >>= 1) m = fmaxf(m, __shfl_xor_sync(0xFFFFFFFFu, m, o));
        if (lane == 0) red[wid] = m;
        __syncthreads();
        float M = red[0];
#pragma unroll
        for (int i = 1; i < 16; i++) M = fmaxf(M, red[i]);
        __syncthreads();

        float s = 0.f;
#pragma unroll
        for (int cj = 0; cj < 4; cj++) s += __expf(logit[rr][cj] - M);
#pragma unroll
        for (int o = 16; o > 0; o >>= 1) s += __shfl_xor_sync(0xFFFFFFFFu, s, o);
        if (lane == 0) red[wid] = s;
        __syncthreads();
        float S = 0.f;
#pragma unroll
        for (int i = 0; i < 16; i++) S += red[i];
        __syncthreads();

        const float lse = M + __logf(S);
        const int t = t0 + rr;
        float4 o4;
        o4.x = logit[rr][0] - lse;
        o4.y = logit[rr][1] - lse;
        o4.z = logit[rr][2] - lse;
        o4.w = logit[rr][3] - lse;
        *reinterpret_cast<float4*>(&out[(size_t)t * EVD + 4 * tid]) = o4;
    }

    // ner_emb and ner_index outputs
    float* out_emb = out + (size_t)T_LEN * EVD;
    float* out_idx = out_emb + (size_t)T_LEN * EMB;
    if (tid < 16 * EMB) {
        const int rr = tid >> 4, j = tid & 15;
        const int t = t0 + rr;
        out_emb[t * EMB + j] = emb[g_idx[t] * EMB + j];
    }
    if (tid < 16) {
        const int t = t0 + tid;
        out_idx[t] = (float)g_idx[t];
    }
}

// ---------------------------------------------------------------------------
extern "C" void kernel_launch(void* const* d_in, const int* in_sizes, int n_in,
                              void* d_out, int out_size) {
    const float* bilstm = (const float*)d_in[0];
    const float* emb    = (const float*)d_in[1];
    const float* W1     = (const float*)d_in[2];
    const float* b1     = (const float*)d_in[3];
    const float* W2     = (const float*)d_in[4];
    const float* b2     = (const float*)d_in[5];
    const int*   init   = (const int*)d_in[6];
    float* out = (float*)d_out;

    // Allow the 16-CTA (non-portable) cluster. Host-side attribute set:
    // executes immediately, not a stream op -> graph-capture safe, idempotent.
    cudaFuncSetAttribute((const void*)seq_kernel,
                         cudaFuncAttributeNonPortableClusterSizeAllowed, 1);

    x_kernel<<<T_LEN / 16, 128>>>(bilstm, W1, b1);
    c_kernel<<<EVD, 128>>>(emb, W1);
    {
        dim3 g(EVD / 32, TMP / 32);
        w2t_kernel<<<g, 256>>>(W2);
    }
    seq_kernel<<<NCTA, NTHR>>>(W2, b2, init);
    out_kernel<<<T_LEN / 16, 512>>>(b2, emb, init, out);
}